// round 1
// baseline (speedup 1.0000x reference)
#include <cuda_runtime.h>
#include <cstdint>

#define QN 16
#define DD 384
#define NCOL 1000000
#define TN 4
#define TPB 256
#define COLS_PER_BLOCK (TPB * TN)
#define NBLK ((NCOL + COLS_PER_BLOCK - 1) / COLS_PER_BLOCK)  // 977

__device__ __forceinline__ float neg_inf() { return __int_as_float(0xff800000); }

// Duplicated L1-normalized queries: g_q2[d*QN + qi] = {qn, qn} for packed f32x2 FMA.
__device__ float2 g_q2[DD * QN];

struct __align__(16) Top2 {
    float v1;
    float v2;
    int   i1;
    int   i2;
};

__device__ Top2 g_part[NBLK * QN];

__device__ __forceinline__ bool before(float va, int ia, float vb, int ib) {
    // strict ordering matching jax top_k: larger value first, lower index on tie
    return (va > vb) || (va == vb && ia < ib);
}

__device__ __forceinline__ void merge_one(float& v1, int& i1, float& v2, int& i2,
                                          float s, int idx) {
    if (before(s, idx, v1, i1)) {
        v2 = v1; i2 = i1; v1 = s; i1 = idx;
    } else if (before(s, idx, v2, i2)) {
        v2 = s; i2 = idx;
    }
}

__device__ __forceinline__ void merge_pair(float& v1, int& i1, float& v2, int& i2,
                                           float w1, int j1, float w2, int j2) {
    merge_one(v1, i1, v2, i2, w1, j1);
    merge_one(v1, i1, v2, i2, w2, j2);
}

// ---------------------------------------------------------------------------
// Kernel 1: L1-normalize the 16 query rows, write duplicated pairs [d][qi].
// ---------------------------------------------------------------------------
__global__ void qnorm_kernel(const float* __restrict__ q) {
    int w = threadIdx.x >> 5;
    int lane = threadIdx.x & 31;
    if (w >= QN) return;
    float s = 0.f;
    #pragma unroll
    for (int d = lane; d < DD; d += 32) s += fabsf(q[w * DD + d]);
    #pragma unroll
    for (int o = 16; o; o >>= 1) s += __shfl_xor_sync(0xffffffffu, s, o);
    s = fmaxf(s, 1e-12f);
    #pragma unroll
    for (int d = lane; d < DD; d += 32) {
        float v = q[w * DD + d] / s;
        g_q2[d * QN + w] = make_float2(v, v);
    }
}

// ---------------------------------------------------------------------------
// Kernel 2: streaming similarity + per-block top-2.
// Each thread owns 4 consecutive columns; accumulates 16 queries via f32x2 FMA.
// ---------------------------------------------------------------------------
__global__ __launch_bounds__(TPB) void sim_kernel(const float* __restrict__ bank,
                                                  const int* __restrict__ startp,
                                                  const int* __restrict__ endp) {
    __shared__ float2 qs2[DD * QN];  // 48 KB
    for (int i = threadIdx.x; i < DD * QN; i += TPB) qs2[i] = g_q2[i];
    __syncthreads();

    const int start = startp ? *startp : 400000;
    const int end   = endp   ? *endp   : 450000;

    const int n0 = blockIdx.x * COLS_PER_BLOCK + threadIdx.x * TN;

    unsigned long long acc01[QN], acc23[QN];
    #pragma unroll
    for (int i = 0; i < QN; ++i) { acc01[i] = 0ull; acc23[i] = 0ull; }

    const bool active = (n0 < NCOL) && !(n0 >= start && n0 + TN <= end);
    if (active) {
        const float* pf = bank + n0;
        const unsigned long long* qsu =
            reinterpret_cast<const unsigned long long*>(qs2);
        #pragma unroll 1
        for (int d = 0; d < DD; ++d) {
            float4 b = __ldcs(reinterpret_cast<const float4*>(pf));
            pf += NCOL;
            unsigned long long b01, b23;
            asm("mov.b64 %0, {%1, %2};" : "=l"(b01) : "f"(b.x), "f"(b.y));
            asm("mov.b64 %0, {%1, %2};" : "=l"(b23) : "f"(b.z), "f"(b.w));
            const unsigned long long* qrow = qsu + d * QN;
            #pragma unroll
            for (int qi = 0; qi < QN; ++qi) {
                unsigned long long q2 = qrow[qi];
                asm("fma.rn.f32x2 %0, %1, %2, %0;"
                    : "+l"(acc01[qi]) : "l"(q2), "l"(b01));
                asm("fma.rn.f32x2 %0, %1, %2, %0;"
                    : "+l"(acc23[qi]) : "l"(q2), "l"(b23));
            }
        }
    }

    bool ok[TN];
    #pragma unroll
    for (int c = 0; c < TN; ++c) {
        int col = n0 + c;
        ok[c] = active && (col < NCOL) && !(col >= start && col < end);
    }

    __syncthreads();  // done reading qs2 — reuse as reduction scratch
    Top2* sred = reinterpret_cast<Top2*>(qs2);  // [TPB/32][QN] = 2 KB
    const int warp = threadIdx.x >> 5;
    const int lane = threadIdx.x & 31;

    #pragma unroll
    for (int qi = 0; qi < QN; ++qi) {
        float a0, a1, a2, a3;
        asm("mov.b64 {%0, %1}, %2;" : "=f"(a0), "=f"(a1) : "l"(acc01[qi]));
        asm("mov.b64 {%0, %1}, %2;" : "=f"(a2), "=f"(a3) : "l"(acc23[qi]));
        float v1 = neg_inf(), v2 = neg_inf();
        int i1 = 0x7fffffff, i2 = 0x7fffffff;
        if (ok[0]) merge_one(v1, i1, v2, i2, a0, n0 + 0);
        if (ok[1]) merge_one(v1, i1, v2, i2, a1, n0 + 1);
        if (ok[2]) merge_one(v1, i1, v2, i2, a2, n0 + 2);
        if (ok[3]) merge_one(v1, i1, v2, i2, a3, n0 + 3);
        #pragma unroll
        for (int off = 16; off; off >>= 1) {
            float w1 = __shfl_down_sync(0xffffffffu, v1, off);
            int   j1 = __shfl_down_sync(0xffffffffu, i1, off);
            float w2 = __shfl_down_sync(0xffffffffu, v2, off);
            int   j2 = __shfl_down_sync(0xffffffffu, i2, off);
            merge_pair(v1, i1, v2, i2, w1, j1, w2, j2);
        }
        if (lane == 0) {
            Top2 t; t.v1 = v1; t.v2 = v2; t.i1 = i1; t.i2 = i2;
            sred[warp * QN + qi] = t;
        }
    }
    __syncthreads();

    if (threadIdx.x < QN) {
        const int qi = threadIdx.x;
        float v1 = neg_inf(), v2 = neg_inf();
        int i1 = 0x7fffffff, i2 = 0x7fffffff;
        #pragma unroll
        for (int w = 0; w < TPB / 32; ++w) {
            Top2 t = sred[w * QN + qi];
            merge_pair(v1, i1, v2, i2, t.v1, t.i1, t.v2, t.i2);
        }
        Top2 r; r.v1 = v1; r.v2 = v2; r.i1 = i1; r.i2 = i2;
        g_part[blockIdx.x * QN + qi] = r;
    }
}

// ---------------------------------------------------------------------------
// Kernel 3: final merge of per-block candidates; write values then indices.
// Output layout: out[0..31] = values[16][2], out[32..63] = indices as float.
// ---------------------------------------------------------------------------
__global__ void final_kernel(float* __restrict__ out, int nblocks) {
    int w = threadIdx.x >> 5;
    int lane = threadIdx.x & 31;
    if (w >= QN) return;
    float v1 = neg_inf(), v2 = neg_inf();
    int i1 = 0x7fffffff, i2 = 0x7fffffff;
    for (int b = lane; b < nblocks; b += 32) {
        Top2 t = g_part[b * QN + w];
        merge_pair(v1, i1, v2, i2, t.v1, t.i1, t.v2, t.i2);
    }
    #pragma unroll
    for (int off = 16; off; off >>= 1) {
        float w1 = __shfl_down_sync(0xffffffffu, v1, off);
        int   j1 = __shfl_down_sync(0xffffffffu, i1, off);
        float w2 = __shfl_down_sync(0xffffffffu, v2, off);
        int   j2 = __shfl_down_sync(0xffffffffu, i2, off);
        merge_pair(v1, i1, v2, i2, w1, j1, w2, j2);
    }
    if (lane == 0) {
        out[w * 2 + 0] = v1;
        out[w * 2 + 1] = v2;
        out[QN * 2 + w * 2 + 0] = (float)i1;
        out[QN * 2 + w * 2 + 1] = (float)i2;
    }
}

extern "C" void kernel_launch(void* const* d_in, const int* in_sizes, int n_in,
                              void* d_out, int out_size) {
    const float* q    = (const float*)d_in[0];
    const float* bank = (const float*)d_in[1];
    const int* startp = (n_in > 2) ? (const int*)d_in[2] : nullptr;
    const int* endp   = (n_in > 3) ? (const int*)d_in[3] : nullptr;
    float* out = (float*)d_out;

    qnorm_kernel<<<1, 512>>>(q);
    sim_kernel<<<NBLK, TPB>>>(bank, startp, endp);
    final_kernel<<<1, 512>>>(out, NBLK);
}

// round 2
// speedup vs baseline: 1.4381x; 1.4381x over previous
#include <cuda_runtime.h>
#include <cstdint>

#define QN 16
#define DD 384
#define NCOL 1000000
#define TN 4
#define TPB 256
#define PREF 4
#define COLS_PER_BLOCK (TPB * TN)
#define NBLK ((NCOL + COLS_PER_BLOCK - 1) / COLS_PER_BLOCK)  // 977

__device__ __forceinline__ float neg_inf() { return __int_as_float(0xff800000); }

// Duplicated L1-normalized queries: g_q2[d*QN + qi] = {qn, qn} for packed f32x2 FMA.
__device__ float2 g_q2[DD * QN];

struct __align__(16) Top2 {
    float v1;
    float v2;
    int   i1;
    int   i2;
};

__device__ Top2 g_part[NBLK * QN];

__device__ __forceinline__ bool before(float va, int ia, float vb, int ib) {
    return (va > vb) || (va == vb && ia < ib);
}

__device__ __forceinline__ void merge_one(float& v1, int& i1, float& v2, int& i2,
                                          float s, int idx) {
    if (before(s, idx, v1, i1)) {
        v2 = v1; i2 = i1; v1 = s; i1 = idx;
    } else if (before(s, idx, v2, i2)) {
        v2 = s; i2 = idx;
    }
}

__device__ __forceinline__ void merge_pair(float& v1, int& i1, float& v2, int& i2,
                                           float w1, int j1, float w2, int j2) {
    merge_one(v1, i1, v2, i2, w1, j1);
    merge_one(v1, i1, v2, i2, w2, j2);
}

// ---------------------------------------------------------------------------
// Kernel 1: L1-normalize the 16 query rows, write duplicated pairs [d][qi].
// ---------------------------------------------------------------------------
__global__ void qnorm_kernel(const float* __restrict__ q) {
    int w = threadIdx.x >> 5;
    int lane = threadIdx.x & 31;
    if (w >= QN) return;
    float s = 0.f;
    #pragma unroll
    for (int d = lane; d < DD; d += 32) s += fabsf(q[w * DD + d]);
    #pragma unroll
    for (int o = 16; o; o >>= 1) s += __shfl_xor_sync(0xffffffffu, s, o);
    s = fmaxf(s, 1e-12f);
    #pragma unroll
    for (int d = lane; d < DD; d += 32) {
        float v = q[w * DD + d] / s;
        g_q2[d * QN + w] = make_float2(v, v);
    }
}

// ---------------------------------------------------------------------------
// Kernel 2: streaming similarity + per-block top-2.
// Depth-4 register prefetch ring on the bank stream (MLP=4 per thread),
// LDS.128 query loads, f32x2 packed FMA accumulation.
// ---------------------------------------------------------------------------
__global__ __launch_bounds__(TPB) void sim_kernel(const float* __restrict__ bank,
                                                  const int* __restrict__ startp,
                                                  const int* __restrict__ endp) {
    __shared__ __align__(16) float2 qs2[DD * QN];  // 48 KB
    for (int i = threadIdx.x; i < DD * QN; i += TPB) qs2[i] = g_q2[i];
    __syncthreads();

    const int start = startp ? *startp : 400000;
    const int end   = endp   ? *endp   : 450000;

    const int n0 = blockIdx.x * COLS_PER_BLOCK + threadIdx.x * TN;

    unsigned long long acc01[QN], acc23[QN];
    #pragma unroll
    for (int i = 0; i < QN; ++i) { acc01[i] = 0ull; acc23[i] = 0ull; }

    const bool active = (n0 < NCOL) && !(n0 >= start && n0 + TN <= end);
    if (active) {
        const float* p0 = bank + n0;
        float4 buf[PREF];
        #pragma unroll
        for (int p = 0; p < PREF; ++p)
            buf[p] = __ldcs(reinterpret_cast<const float4*>(p0 + (size_t)p * NCOL));
        const float* ppref = p0 + (size_t)PREF * NCOL;

        const ulonglong2* qsu = reinterpret_cast<const ulonglong2*>(qs2);

        #pragma unroll 4
        for (int d = 0; d < DD - PREF; ++d) {
            float4 b = buf[d & (PREF - 1)];
            // prefetch d+PREF (independent of compute below)
            buf[d & (PREF - 1)] =
                __ldcs(reinterpret_cast<const float4*>(ppref));
            ppref += NCOL;

            unsigned long long b01, b23;
            asm("mov.b64 %0, {%1, %2};" : "=l"(b01) : "f"(b.x), "f"(b.y));
            asm("mov.b64 %0, {%1, %2};" : "=l"(b23) : "f"(b.z), "f"(b.w));
            const ulonglong2* qrow2 = qsu + d * (QN / 2);
            #pragma unroll
            for (int qi = 0; qi < QN; qi += 2) {
                ulonglong2 qq = qrow2[qi >> 1];
                asm("fma.rn.f32x2 %0, %1, %2, %0;"
                    : "+l"(acc01[qi]) : "l"(qq.x), "l"(b01));
                asm("fma.rn.f32x2 %0, %1, %2, %0;"
                    : "+l"(acc23[qi]) : "l"(qq.x), "l"(b23));
                asm("fma.rn.f32x2 %0, %1, %2, %0;"
                    : "+l"(acc01[qi + 1]) : "l"(qq.y), "l"(b01));
                asm("fma.rn.f32x2 %0, %1, %2, %0;"
                    : "+l"(acc23[qi + 1]) : "l"(qq.y), "l"(b23));
            }
        }
        // epilogue: drain the ring, no more prefetches
        #pragma unroll
        for (int d = DD - PREF; d < DD; ++d) {
            float4 b = buf[d & (PREF - 1)];
            unsigned long long b01, b23;
            asm("mov.b64 %0, {%1, %2};" : "=l"(b01) : "f"(b.x), "f"(b.y));
            asm("mov.b64 %0, {%1, %2};" : "=l"(b23) : "f"(b.z), "f"(b.w));
            const ulonglong2* qrow2 = qsu + d * (QN / 2);
            #pragma unroll
            for (int qi = 0; qi < QN; qi += 2) {
                ulonglong2 qq = qrow2[qi >> 1];
                asm("fma.rn.f32x2 %0, %1, %2, %0;"
                    : "+l"(acc01[qi]) : "l"(qq.x), "l"(b01));
                asm("fma.rn.f32x2 %0, %1, %2, %0;"
                    : "+l"(acc23[qi]) : "l"(qq.x), "l"(b23));
                asm("fma.rn.f32x2 %0, %1, %2, %0;"
                    : "+l"(acc01[qi + 1]) : "l"(qq.y), "l"(b01));
                asm("fma.rn.f32x2 %0, %1, %2, %0;"
                    : "+l"(acc23[qi + 1]) : "l"(qq.y), "l"(b23));
            }
        }
    }

    bool ok[TN];
    #pragma unroll
    for (int c = 0; c < TN; ++c) {
        int col = n0 + c;
        ok[c] = active && (col < NCOL) && !(col >= start && col < end);
    }

    __syncthreads();  // done reading qs2 — reuse as reduction scratch
    Top2* sred = reinterpret_cast<Top2*>(qs2);  // [TPB/32][QN] = 2 KB
    const int warp = threadIdx.x >> 5;
    const int lane = threadIdx.x & 31;

    #pragma unroll
    for (int qi = 0; qi < QN; ++qi) {
        float a0, a1, a2, a3;
        asm("mov.b64 {%0, %1}, %2;" : "=f"(a0), "=f"(a1) : "l"(acc01[qi]));
        asm("mov.b64 {%0, %1}, %2;" : "=f"(a2), "=f"(a3) : "l"(acc23[qi]));
        float v1 = neg_inf(), v2 = neg_inf();
        int i1 = 0x7fffffff, i2 = 0x7fffffff;
        if (ok[0]) merge_one(v1, i1, v2, i2, a0, n0 + 0);
        if (ok[1]) merge_one(v1, i1, v2, i2, a1, n0 + 1);
        if (ok[2]) merge_one(v1, i1, v2, i2, a2, n0 + 2);
        if (ok[3]) merge_one(v1, i1, v2, i2, a3, n0 + 3);
        #pragma unroll
        for (int off = 16; off; off >>= 1) {
            float w1 = __shfl_down_sync(0xffffffffu, v1, off);
            int   j1 = __shfl_down_sync(0xffffffffu, i1, off);
            float w2 = __shfl_down_sync(0xffffffffu, v2, off);
            int   j2 = __shfl_down_sync(0xffffffffu, i2, off);
            merge_pair(v1, i1, v2, i2, w1, j1, w2, j2);
        }
        if (lane == 0) {
            Top2 t; t.v1 = v1; t.v2 = v2; t.i1 = i1; t.i2 = i2;
            sred[warp * QN + qi] = t;
        }
    }
    __syncthreads();

    if (threadIdx.x < QN) {
        const int qi = threadIdx.x;
        float v1 = neg_inf(), v2 = neg_inf();
        int i1 = 0x7fffffff, i2 = 0x7fffffff;
        #pragma unroll
        for (int w = 0; w < TPB / 32; ++w) {
            Top2 t = sred[w * QN + qi];
            merge_pair(v1, i1, v2, i2, t.v1, t.i1, t.v2, t.i2);
        }
        Top2 r; r.v1 = v1; r.v2 = v2; r.i1 = i1; r.i2 = i2;
        g_part[blockIdx.x * QN + qi] = r;
    }
}

// ---------------------------------------------------------------------------
// Kernel 3: final merge of per-block candidates; write values then indices.
// ---------------------------------------------------------------------------
__global__ void final_kernel(float* __restrict__ out, int nblocks) {
    int w = threadIdx.x >> 5;
    int lane = threadIdx.x & 31;
    if (w >= QN) return;
    float v1 = neg_inf(), v2 = neg_inf();
    int i1 = 0x7fffffff, i2 = 0x7fffffff;
    for (int b = lane; b < nblocks; b += 32) {
        Top2 t = g_part[b * QN + w];
        merge_pair(v1, i1, v2, i2, t.v1, t.i1, t.v2, t.i2);
    }
    #pragma unroll
    for (int off = 16; off; off >>= 1) {
        float w1 = __shfl_down_sync(0xffffffffu, v1, off);
        int   j1 = __shfl_down_sync(0xffffffffu, i1, off);
        float w2 = __shfl_down_sync(0xffffffffu, v2, off);
        int   j2 = __shfl_down_sync(0xffffffffu, i2, off);
        merge_pair(v1, i1, v2, i2, w1, j1, w2, j2);
    }
    if (lane == 0) {
        out[w * 2 + 0] = v1;
        out[w * 2 + 1] = v2;
        out[QN * 2 + w * 2 + 0] = (float)i1;
        out[QN * 2 + w * 2 + 1] = (float)i2;
    }
}

extern "C" void kernel_launch(void* const* d_in, const int* in_sizes, int n_in,
                              void* d_out, int out_size) {
    const float* q    = (const float*)d_in[0];
    const float* bank = (const float*)d_in[1];
    const int* startp = (n_in > 2) ? (const int*)d_in[2] : nullptr;
    const int* endp   = (n_in > 3) ? (const int*)d_in[3] : nullptr;
    float* out = (float*)d_out;

    qnorm_kernel<<<1, 512>>>(q);
    sim_kernel<<<NBLK, TPB>>>(bank, startp, endp);
    final_kernel<<<1, 512>>>(out, NBLK);
}

// round 3
// speedup vs baseline: 1.6895x; 1.1748x over previous
#include <cuda_runtime.h>
#include <cstdint>

#define QN 16
#define QP 8            // query pairs
#define DD 384
#define NCOL 1000000
#define TN 4
#define TPB 256
#define PREF 8
#define COLS_PER_BLOCK (TPB * TN)
#define NBLK ((NCOL + COLS_PER_BLOCK - 1) / COLS_PER_BLOCK)  // 977

__device__ __forceinline__ float neg_inf() { return __int_as_float(0xff800000); }

struct __align__(16) Top2 {
    float v1;
    float v2;
    int   i1;
    int   i2;
};

__device__ Top2 g_part[NBLK * QN];

__device__ __forceinline__ bool before(float va, int ia, float vb, int ib) {
    return (va > vb) || (va == vb && ia < ib);
}

__device__ __forceinline__ void merge_one(float& v1, int& i1, float& v2, int& i2,
                                          float s, int idx) {
    if (before(s, idx, v1, i1)) {
        v2 = v1; i2 = i1; v1 = s; i1 = idx;
    } else if (before(s, idx, v2, i2)) {
        v2 = s; i2 = idx;
    }
}

__device__ __forceinline__ void merge_pair(float& v1, int& i1, float& v2, int& i2,
                                           float w1, int j1, float w2, int j2) {
    merge_one(v1, i1, v2, i2, w1, j1);
    merge_one(v1, i1, v2, i2, w2, j2);
}

// ---------------------------------------------------------------------------
// Main kernel: per-block q-normalization preamble, then streaming similarity
// with depth-8 register prefetch ring + query-pair packed f32x2 FMAs.
// ---------------------------------------------------------------------------
__global__ __launch_bounds__(TPB, 2) void sim_kernel(const float* __restrict__ q,
                                                     const float* __restrict__ bank,
                                                     const int* __restrict__ startp,
                                                     const int* __restrict__ endp) {
    // qs[d][p] = {qn[2p][d], qn[2p+1][d]}  (24 KB)
    __shared__ __align__(16) float2 qs[DD * QP];

    // --- preamble: L1-normalize queries (each warp owns query pair w) ---
    {
        const int w = threadIdx.x >> 5;    // 0..7 = pair index
        const int lane = threadIdx.x & 31;
        const float* q0 = q + (2 * w) * DD;
        const float* q1 = q + (2 * w + 1) * DD;
        float s0 = 0.f, s1 = 0.f;
        #pragma unroll
        for (int d = lane; d < DD; d += 32) {
            s0 += fabsf(q0[d]);
            s1 += fabsf(q1[d]);
        }
        #pragma unroll
        for (int o = 16; o; o >>= 1) {
            s0 += __shfl_xor_sync(0xffffffffu, s0, o);
            s1 += __shfl_xor_sync(0xffffffffu, s1, o);
        }
        const float inv0 = 1.0f / fmaxf(s0, 1e-12f);
        const float inv1 = 1.0f / fmaxf(s1, 1e-12f);
        #pragma unroll
        for (int d = lane; d < DD; d += 32)
            qs[d * QP + w] = make_float2(q0[d] * inv0, q1[d] * inv1);
    }
    __syncthreads();

    const int start = startp ? *startp : 400000;
    const int end   = endp   ? *endp   : 450000;

    const int n0 = blockIdx.x * COLS_PER_BLOCK + threadIdx.x * TN;

    // acc[p][c] = {sim[2p][n0+c], sim[2p+1][n0+c]}
    unsigned long long acc[QP][TN];
    #pragma unroll
    for (int p = 0; p < QP; ++p)
        #pragma unroll
        for (int c = 0; c < TN; ++c) acc[p][c] = 0ull;

    const bool active = (n0 < NCOL) && !(n0 >= start && n0 + TN <= end);
    if (active) {
        const float* p0 = bank + n0;
        float4 buf[PREF];
        #pragma unroll
        for (int p = 0; p < PREF; ++p)
            buf[p] = __ldcs(reinterpret_cast<const float4*>(p0 + (size_t)p * NCOL));
        const float* ppref = p0 + (size_t)PREF * NCOL;

        const ulonglong2* qsu = reinterpret_cast<const ulonglong2*>(qs);

        #pragma unroll 8
        for (int d = 0; d < DD - PREF; ++d) {
            float4 b = buf[d & (PREF - 1)];
            buf[d & (PREF - 1)] = __ldcs(reinterpret_cast<const float4*>(ppref));
            ppref += NCOL;

            unsigned long long bd[TN];
            asm("mov.b64 %0, {%1, %1};" : "=l"(bd[0]) : "f"(b.x));
            asm("mov.b64 %0, {%1, %1};" : "=l"(bd[1]) : "f"(b.y));
            asm("mov.b64 %0, {%1, %1};" : "=l"(bd[2]) : "f"(b.z));
            asm("mov.b64 %0, {%1, %1};" : "=l"(bd[3]) : "f"(b.w));

            const ulonglong2* qrow = qsu + d * (QP / 2);
            #pragma unroll
            for (int ph = 0; ph < QP / 2; ++ph) {
                ulonglong2 qq = qrow[ph];
                #pragma unroll
                for (int c = 0; c < TN; ++c)
                    asm("fma.rn.f32x2 %0, %1, %2, %0;"
                        : "+l"(acc[2 * ph][c]) : "l"(qq.x), "l"(bd[c]));
                #pragma unroll
                for (int c = 0; c < TN; ++c)
                    asm("fma.rn.f32x2 %0, %1, %2, %0;"
                        : "+l"(acc[2 * ph + 1][c]) : "l"(qq.y), "l"(bd[c]));
            }
        }
        // drain ring
        #pragma unroll
        for (int d = DD - PREF; d < DD; ++d) {
            float4 b = buf[d & (PREF - 1)];
            unsigned long long bd[TN];
            asm("mov.b64 %0, {%1, %1};" : "=l"(bd[0]) : "f"(b.x));
            asm("mov.b64 %0, {%1, %1};" : "=l"(bd[1]) : "f"(b.y));
            asm("mov.b64 %0, {%1, %1};" : "=l"(bd[2]) : "f"(b.z));
            asm("mov.b64 %0, {%1, %1};" : "=l"(bd[3]) : "f"(b.w));
            const ulonglong2* qrow = qsu + d * (QP / 2);
            #pragma unroll
            for (int ph = 0; ph < QP / 2; ++ph) {
                ulonglong2 qq = qrow[ph];
                #pragma unroll
                for (int c = 0; c < TN; ++c)
                    asm("fma.rn.f32x2 %0, %1, %2, %0;"
                        : "+l"(acc[2 * ph][c]) : "l"(qq.x), "l"(bd[c]));
                #pragma unroll
                for (int c = 0; c < TN; ++c)
                    asm("fma.rn.f32x2 %0, %1, %2, %0;"
                        : "+l"(acc[2 * ph + 1][c]) : "l"(qq.y), "l"(bd[c]));
            }
        }
    }

    bool ok[TN];
    #pragma unroll
    for (int c = 0; c < TN; ++c) {
        int col = n0 + c;
        ok[c] = active && (col < NCOL) && !(col >= start && col < end);
    }

    __syncthreads();  // done reading qs — reuse as reduction scratch
    Top2* sred = reinterpret_cast<Top2*>(qs);  // [8 warps][16 queries]
    const int warp = threadIdx.x >> 5;
    const int lane = threadIdx.x & 31;

    #pragma unroll
    for (int qi = 0; qi < QN; ++qi) {
        const int p = qi >> 1;
        const int h = qi & 1;
        float a[TN];
        #pragma unroll
        for (int c = 0; c < TN; ++c) {
            float lo, hi;
            asm("mov.b64 {%0, %1}, %2;" : "=f"(lo), "=f"(hi) : "l"(acc[p][c]));
            a[c] = h ? hi : lo;
        }
        float v1 = neg_inf(), v2 = neg_inf();
        int i1 = 0x7fffffff, i2 = 0x7fffffff;
        #pragma unroll
        for (int c = 0; c < TN; ++c)
            if (ok[c]) merge_one(v1, i1, v2, i2, a[c], n0 + c);
        #pragma unroll
        for (int off = 16; off; off >>= 1) {
            float w1 = __shfl_down_sync(0xffffffffu, v1, off);
            int   j1 = __shfl_down_sync(0xffffffffu, i1, off);
            float w2 = __shfl_down_sync(0xffffffffu, v2, off);
            int   j2 = __shfl_down_sync(0xffffffffu, i2, off);
            merge_pair(v1, i1, v2, i2, w1, j1, w2, j2);
        }
        if (lane == 0) {
            Top2 t; t.v1 = v1; t.v2 = v2; t.i1 = i1; t.i2 = i2;
            sred[warp * QN + qi] = t;
        }
    }
    __syncthreads();

    if (threadIdx.x < QN) {
        const int qi = threadIdx.x;
        float v1 = neg_inf(), v2 = neg_inf();
        int i1 = 0x7fffffff, i2 = 0x7fffffff;
        #pragma unroll
        for (int w = 0; w < TPB / 32; ++w) {
            Top2 t = sred[w * QN + qi];
            merge_pair(v1, i1, v2, i2, t.v1, t.i1, t.v2, t.i2);
        }
        Top2 r; r.v1 = v1; r.v2 = v2; r.i1 = i1; r.i2 = i2;
        g_part[blockIdx.x * QN + qi] = r;
    }
}

// ---------------------------------------------------------------------------
// Final merge of per-block candidates; values then indices (as float).
// ---------------------------------------------------------------------------
__global__ void final_kernel(float* __restrict__ out, int nblocks) {
    int w = threadIdx.x >> 5;
    int lane = threadIdx.x & 31;
    if (w >= QN) return;
    float v1 = neg_inf(), v2 = neg_inf();
    int i1 = 0x7fffffff, i2 = 0x7fffffff;
    for (int b = lane; b < nblocks; b += 32) {
        Top2 t = g_part[b * QN + w];
        merge_pair(v1, i1, v2, i2, t.v1, t.i1, t.v2, t.i2);
    }
    #pragma unroll
    for (int off = 16; off; off >>= 1) {
        float w1 = __shfl_down_sync(0xffffffffu, v1, off);
        int   j1 = __shfl_down_sync(0xffffffffu, i1, off);
        float w2 = __shfl_down_sync(0xffffffffu, v2, off);
        int   j2 = __shfl_down_sync(0xffffffffu, i2, off);
        merge_pair(v1, i1, v2, i2, w1, j1, w2, j2);
    }
    if (lane == 0) {
        out[w * 2 + 0] = v1;
        out[w * 2 + 1] = v2;
        out[QN * 2 + w * 2 + 0] = (float)i1;
        out[QN * 2 + w * 2 + 1] = (float)i2;
    }
}

extern "C" void kernel_launch(void* const* d_in, const int* in_sizes, int n_in,
                              void* d_out, int out_size) {
    const float* q    = (const float*)d_in[0];
    const float* bank = (const float*)d_in[1];
    const int* startp = (n_in > 2) ? (const int*)d_in[2] : nullptr;
    const int* endp   = (n_in > 3) ? (const int*)d_in[3] : nullptr;
    float* out = (float*)d_out;

    sim_kernel<<<NBLK, TPB>>>(q, bank, startp, endp);
    final_kernel<<<1, 512>>>(out, NBLK);
}